// round 16
// baseline (speedup 1.0000x reference)
#include <cuda_runtime.h>
#include <cuda_fp16.h>
#include <cstdint>

// Problem constants
#define Bb 64
#define Ii 2048
#define Oo 2048
#define Ss 10
#define Cc 512

// Tiling
#define No 8                  // o's per CTA -> N = 96 cols
#define NCOL 12               // cols per o: 10 seg + w + pad
#define KCH 64                // K chunk
#define NCHUNKS (Ii / KCH)    // 32
#define STAGES 4

// smem layout (byte offsets from 1024-aligned base)
#define A_TILE 8192           // 64 rows x 128 B (fp16 [b][k] SW128)
#define B_TILE 12288          // 96 rows x 128 B (fp16 [n][k] SW128)
#define SM_BAR 0              // full[st]@st*8 (0..24), empty[st]@32+st*8 (32..56)
#define SM_A 1024
#define SM_B (SM_A + STAGES * A_TILE)      // 33792
#define SM_EP SM_A            // epilogue fp32 [64][EPW] overlays A region (post-loop only)
#define EPW 100
#define SM_MA (SM_EP + Bb * EPW * 4)       // 8 floats mean-astro (post-loop only)
#define SM_CTX (SM_B + STAGES * B_TILE)    // 82944: 64 ctx means (dedicated, persists)
#define SMEM_REQ (SM_CTX + 256 + 768)      // 83968 (x2 CTAs/SM = 168KB)

#define NTHREADS 256          // warps 0-3 consumers (MMA), 4-7 producers

// -------- helpers --------
__device__ __forceinline__ uint32_t sa(const void* p) {
    return (uint32_t)__cvta_generic_to_shared(p);
}
__device__ __forceinline__ uint32_t cvt_f16x2(float hi, float lo) {
    uint32_t r;
    asm("cvt.rn.f16x2.f32 %0, %1, %2;" : "=r"(r) : "f"(hi), "f"(lo));
    return r;
}
__device__ __forceinline__ void sts64(uint32_t addr, uint32_t lo, uint32_t hi) {
    asm volatile("{\n\t.reg .b64 v;\n\tmov.b64 v, {%1, %2};\n\t"
                 "st.shared.b64 [%0], v;\n\t}" :: "r"(addr), "r"(lo), "r"(hi) : "memory");
}
__device__ __forceinline__ void stsv2(uint32_t addr, float x, float y) {
    asm volatile("st.shared.v2.f32 [%0], {%1, %2};" :: "r"(addr), "f"(x), "f"(y) : "memory");
}
__device__ __forceinline__ void stsz16(uint32_t addr) {
    asm volatile("st.shared.v4.b32 [%0], {%1, %1, %1, %1};" :: "r"(addr), "r"(0u) : "memory");
}
__device__ __forceinline__ uint32_t swz(uint32_t off) {
    return off ^ ((off >> 3) & 0x70);
}
__device__ __forceinline__ float sigmoidf_(float z) {
    return 1.0f / (1.0f + __expf(-z));
}
__device__ __forceinline__ void ldsm4(uint32_t* r, uint32_t addr) {
    asm volatile("ldmatrix.sync.aligned.m8n8.x4.shared.b16 {%0,%1,%2,%3}, [%4];"
                 : "=r"(r[0]), "=r"(r[1]), "=r"(r[2]), "=r"(r[3]) : "r"(addr));
}
__device__ __forceinline__ void hmma(float* c, const uint32_t* a, const uint32_t* b) {
    asm volatile(
        "mma.sync.aligned.m16n8k16.row.col.f32.f16.f16.f32 "
        "{%0,%1,%2,%3}, {%4,%5,%6,%7}, {%8,%9}, {%0,%1,%2,%3};"
        : "+f"(c[0]), "+f"(c[1]), "+f"(c[2]), "+f"(c[3])
        : "r"(a[0]), "r"(a[1]), "r"(a[2]), "r"(a[3]), "r"(b[0]), "r"(b[1]));
}
__device__ __forceinline__ void mbar_init(uint32_t a, uint32_t cnt) {
    asm volatile("mbarrier.init.shared.b64 [%0], %1;" :: "r"(a), "r"(cnt) : "memory");
}
__device__ __forceinline__ void mbar_arrive(uint32_t a) {
    asm volatile("mbarrier.arrive.release.cta.shared::cta.b64 _, [%0];" :: "r"(a) : "memory");
}
__device__ __forceinline__ void mbar_wait(uint32_t a, uint32_t parity) {
    asm volatile(
        "{\n\t.reg .pred P1;\n\t"
        "WL_%=:\n\t"
        "mbarrier.try_wait.parity.acquire.cta.shared::cta.b64 P1, [%0], %1, 0x989680;\n\t"
        "@P1 bra.uni WD_%=;\n\t"
        "bra.uni WL_%=;\n\t"
        "WD_%=:\n\t}"
        :: "r"(a), "r"(parity) : "memory");
}
__device__ __forceinline__ void barsync(int id, int cnt) {
    asm volatile("bar.sync %0, %1;" :: "r"(id), "r"(cnt) : "memory");
}

// -------- single fused kernel --------
// Grid 256 (No=8), 2 CTAs/SM. Warps 0-3: MMA consumers (also compute ctx means
// during pipeline warm-up). Warps 4-7: producers — D LDGs hoisted ABOVE the
// ring backpressure wait so DRAM stays busy during the wait; x fp32 converted
// to fp16 inline (L2-resident), no prep kernel, no device scratch.
__global__ void __launch_bounds__(NTHREADS, 2)
k_main(const float* __restrict__ dend,
       const float* __restrict__ weight,
       const float* __restrict__ cstr,
       const float* __restrict__ pthr,
       const float* __restrict__ gates,
       const float* __restrict__ bias,
       const float* __restrict__ aact,
       const float* __restrict__ athr,
       const float* __restrict__ ctx,
       const float* __restrict__ x,
       float* __restrict__ out) {
    extern __shared__ char smraw[];
    uint32_t sb0 = sa(smraw);
    uint32_t sb = (sb0 + 1023u) & ~1023u;
    char* smbase = smraw + (sb - sb0);
    float* epf = reinterpret_cast<float*>(smbase + SM_EP);
    float* maf = reinterpret_cast<float*>(smbase + SM_MA);
    float* ctxm = reinterpret_cast<float*>(smbase + SM_CTX);

    const int t = threadIdx.x;
    const int lane = t & 31;
    const int o_base = blockIdx.x * No;

    const uint32_t FULLB = sb + SM_BAR;        // full[0..3] @ 0,8,16,24
    const uint32_t EMPTYB = sb + SM_BAR + 32;  // empty[0..3] @ 32,40,48,56
    const uint32_t aT0 = sb + SM_A;
    const uint32_t bT0 = sb + SM_B;

    if (t < 2 * STAGES) {
        mbar_init(sb + SM_BAR + t * 8, 4u);    // full: 4 prod warps; empty: 4 cons warps
    }
    // zero pad column rows (n % 12 == 11) of all 4 B buffers, once (256 = 4*8*8)
    {
        int st = t >> 6, rem = t & 63, ol = rem >> 3, seg = rem & 7;
        uint32_t n = (uint32_t)(ol * NCOL + 11);
        stsz16(bT0 + st * B_TILE + swz(n * 128 + seg * 16));
    }
    __syncthreads();

    if (t < 128) {
        // ================= CONSUMER (4 warps) =================
        // warm-up: ctx means (overlaps producers filling stage 0)
        {
            const int b = t >> 1, half = t & 1;
            const float4* cp = reinterpret_cast<const float4*>(
                ctx + (size_t)b * Cc + half * (Cc / 2));
            float s = 0.0f;
            #pragma unroll 8
            for (int j = 0; j < Cc / 8; j++) {
                float4 v = cp[j];
                s += (v.x + v.y) + (v.z + v.w);
            }
            s += __shfl_xor_sync(0xffffffffu, s, 1);
            if (half == 0) ctxm[b] = s * (1.0f / Cc);
        }

        const int w = t >> 5;
        const int wm = w & 1;
        const int wn = w >> 1;

        float acc[2][6][4];
        #pragma unroll
        for (int mt = 0; mt < 2; mt++)
            #pragma unroll
            for (int nt = 0; nt < 6; nt++)
                acc[mt][nt][0] = acc[mt][nt][1] = acc[mt][nt][2] = acc[mt][nt][3] = 0.0f;

        const int grp = lane >> 3;
        const uint32_t arow0 = (uint32_t)((wm * 32 + (lane & 15)) * 128 + (lane >> 4) * 16);
        const uint32_t arow1 = arow0 + 16 * 128;
        const uint32_t brow = (uint32_t)((wn * 48 + (grp >> 1) * 8 + (lane & 7)) * 128
                                         + (grp & 1) * 16);

        for (int c = 0; c < NCHUNKS; c++) {
            const int st = c & (STAGES - 1);
            mbar_wait(FULLB + st * 8, (c >> 2) & 1);

            const uint32_t ab = aT0 + st * A_TILE;
            const uint32_t bb = bT0 + st * B_TILE;
            #pragma unroll
            for (int ks = 0; ks < 4; ks++) {
                uint32_t a0[4], a1[4];
                ldsm4(a0, ab + swz(arow0 + ks * 32));
                ldsm4(a1, ab + swz(arow1 + ks * 32));
                #pragma unroll
                for (int pr = 0; pr < 3; pr++) {
                    uint32_t b4[4];
                    ldsm4(b4, bb + swz(brow + (uint32_t)pr * 2048 + ks * 32));
                    hmma(acc[0][2*pr],   a0, b4);
                    hmma(acc[0][2*pr+1], a0, b4 + 2);
                    hmma(acc[1][2*pr],   a1, b4);
                    hmma(acc[1][2*pr+1], a1, b4 + 2);
                }
            }
            __syncwarp();
            if (lane == 0) mbar_arrive(EMPTYB + st * 8);
        }

        // ---- epilogue: dump accumulators, compute mean-astro, combine ----
        barsync(5, 128);
        #pragma unroll
        for (int mt = 0; mt < 2; mt++) {
            int row = wm * 32 + mt * 16 + (lane >> 2);
            #pragma unroll
            for (int nt = 0; nt < 6; nt++) {
                int col = wn * 48 + nt * 8 + 2 * (lane & 3);
                stsv2(sb + SM_EP + (uint32_t)((row * EPW + col) * 4),
                      acc[mt][nt][0], acc[mt][nt][1]);
                stsv2(sb + SM_EP + (uint32_t)(((row + 8) * EPW + col) * 4),
                      acc[mt][nt][2], acc[mt][nt][3]);
            }
        }
        if (t < No) {
            float act = aact[o_base + t];
            float thv = athr[o_base + t];
            float s = 0.0f;
            #pragma unroll 8
            for (int b = 0; b < Bb; b++) {
                float a = 1.0f / (1.0f + expf(-ctxm[b] * act));
                s += (a > thv) ? a : 0.0f;
            }
            maf[t] = s * (1.0f / Bb);
        }
        barsync(5, 128);

        {
            const int ol = t & 7;
            const int bg = t >> 3;          // 0..15
            const int oo = o_base + ol;
            const float ma = maf[ol];
            const float bv = bias[oo];
            float sg[Ss];
            #pragma unroll
            for (int s = 0; s < Ss; s++) sg[s] = sigmoidf_(gates[oo * Ss + s]);
            #pragma unroll
            for (int j = 0; j < 4; j++) {
                int b = bg * 4 + j;
                const float* e = epf + b * EPW + ol * NCOL;
                float v = fmaf(e[10], ma, bv);
                #pragma unroll
                for (int s = 0; s < Ss; s++)
                    v = fmaf(sg[s], fmaxf(e[s], 0.0f), v);
                out[(size_t)b * Oo + oo] = fmaxf(v, 0.0f);
            }
        }
    } else {
        // ================= PRODUCER (4 warps) =================
        const int p = t - 128;           // 0..127
        const int o_loc = p >> 4;        // 0..7
        const int q = p & 15;            // k-quarter: k = 4q..4q+3
        const int o = o_base + o_loc;
        const int nrow = o_loc * NCOL;
        const float thr = pthr[0];
        const float* dsrc = dend + ((size_t)o * Ii + 4 * q) * Ss;
        const float* wsrc = weight + (size_t)o * Ii + 4 * q;
        const float* csrc = cstr + (size_t)o * Ii + 4 * q;

        for (int c = 0; c < NCHUNKS; c++) {
            const int st = c & (STAGES - 1);
            const int kb = c * KCH;

            // HOISTED: one (o, 4k) cell, 12 independent LDG.128 into registers —
            // in flight while we sit in the backpressure wait below.
            float4 d4[10];
            const float4* dp4 = reinterpret_cast<const float4*>(dsrc + (size_t)kb * Ss);
            #pragma unroll
            for (int j = 0; j < 10; j++) d4[j] = dp4[j];
            float4 w4 = *reinterpret_cast<const float4*>(wsrc + kb);
            float4 c4 = *reinterpret_cast<const float4*>(csrc + kb);

            if (c >= STAGES)
                mbar_wait(EMPTYB + st * 8, ((c - STAGES) >> 2) & 1);

            // A tile: x fp32 -> fp16 inline (L2-resident), two halves of 4 float4
            const uint32_t ab = aT0 + st * A_TILE;
            #pragma unroll
            for (int half = 0; half < 2; half++) {
                float4 xv[4];
                #pragma unroll
                for (int r = 0; r < 4; r++) {
                    int idx = p + 128 * (half * 4 + r);   // 0..1023
                    int b = idx >> 4, j = idx & 15;
                    xv[r] = *reinterpret_cast<const float4*>(
                        x + (size_t)b * Ii + kb + j * 4);
                }
                #pragma unroll
                for (int r = 0; r < 4; r++) {
                    int idx = p + 128 * (half * 4 + r);
                    int b = idx >> 4, j = idx & 15;
                    uint32_t h0 = cvt_f16x2(xv[r].y, xv[r].x);
                    uint32_t h1 = cvt_f16x2(xv[r].w, xv[r].z);
                    sts64(ab + swz((uint32_t)b * 128 + j * 8), h0, h1);
                }
            }

            // convert D cell + pruned weight column, STS into B tile
            float f[40];
            #pragma unroll
            for (int j = 0; j < 10; j++) {
                f[4*j] = d4[j].x; f[4*j+1] = d4[j].y;
                f[4*j+2] = d4[j].z; f[4*j+3] = d4[j].w;
            }
            float wv[4];
            wv[0] = (fabsf(w4.x) * c4.x > thr) ? w4.x : 0.0f;
            wv[1] = (fabsf(w4.y) * c4.y > thr) ? w4.y : 0.0f;
            wv[2] = (fabsf(w4.z) * c4.z > thr) ? w4.z : 0.0f;
            wv[3] = (fabsf(w4.w) * c4.w > thr) ? w4.w : 0.0f;

            const uint32_t bb = bT0 + st * B_TILE;
            #pragma unroll
            for (int s = 0; s < 11; s++) {
                float a0, a1, a2, a3;
                if (s < 10) { a0 = f[s]; a1 = f[10+s]; a2 = f[20+s]; a3 = f[30+s]; }
                else        { a0 = wv[0]; a1 = wv[1]; a2 = wv[2]; a3 = wv[3]; }
                uint32_t h0 = cvt_f16x2(a1, a0);
                uint32_t h1 = cvt_f16x2(a3, a2);
                sts64(bb + swz((uint32_t)(nrow + s) * 128 + q * 8), h0, h1);
            }

            __syncwarp();
            if (lane == 0) mbar_arrive(FULLB + st * 8);   // release: all STS visible
        }
    }
}

extern "C" void kernel_launch(void* const* d_in, const int* in_sizes, int n_in,
                              void* d_out, int out_size) {
    const float* x      = (const float*)d_in[0];
    const float* ctx    = (const float*)d_in[1];
    const float* weight = (const float*)d_in[3];
    const float* bias   = (const float*)d_in[4];
    const float* aact   = (const float*)d_in[5];
    const float* athr   = (const float*)d_in[6];
    const float* dend   = (const float*)d_in[7];
    const float* gates  = (const float*)d_in[8];
    const float* cstr   = (const float*)d_in[9];
    const float* pthr   = (const float*)d_in[10];
    float* out = (float*)d_out;

    cudaFuncSetAttribute(k_main, cudaFuncAttributeMaxDynamicSharedMemorySize, SMEM_REQ);

    k_main<<<Oo / No, NTHREADS, SMEM_REQ>>>(dend, weight, cstr, pthr, gates, bias,
                                            aact, athr, ctx, x, out);
}

// round 17
// speedup vs baseline: 1.1979x; 1.1979x over previous
#include <cuda_runtime.h>
#include <cuda_fp16.h>
#include <cstdint>

// Problem constants
#define Bb 64
#define Ii 2048
#define Oo 2048
#define Ss 10
#define Cc 512

// Tiling
#define No 8                  // o's per CTA -> N = 96 cols
#define NCOL 12               // cols per o: 10 seg + w + pad
#define KCH 64                // K chunk
#define NCHUNKS (Ii / KCH)    // 32
#define STAGES 4

// smem layout (byte offsets from 1024-aligned base)
#define A_TILE 8192           // 64 rows x 128 B (fp16 [b][k] SW128)
#define B_TILE 12288          // 96 rows x 128 B (fp16 [n][k] SW128)
#define SM_BAR 0              // full[st]@st*8 (0..24), empty[st]@32+st*8 (32..56)
#define SM_A 1024
#define SM_B (SM_A + STAGES * A_TILE)      // 33792
#define SM_EP SM_A            // epilogue fp32 [64][EPW] overlays A region
#define EPW 100
#define SM_MA (SM_EP + Bb * EPW * 4)
#define SMEM_REQ (SM_B + STAGES * B_TILE + 1024)   // 83968 (x2 CTAs/SM)

#define NTHREADS 256          // warps 0-3 consumers (MMA), 4-7 producers

// -------- scratch globals --------
__device__ float g_ctx_mean[Bb];
__device__ uint32_t g_xh[Bb * Ii / 2];    // fp16x2 [b][k]

// -------- helpers --------
__device__ __forceinline__ uint32_t sa(const void* p) {
    return (uint32_t)__cvta_generic_to_shared(p);
}
__device__ __forceinline__ void cpa16(uint32_t dst, const void* src) {
    asm volatile("cp.async.cg.shared.global [%0], [%1], 16;\n" :: "r"(dst), "l"(src));
}
__device__ __forceinline__ void cpa_commit() {
    asm volatile("cp.async.commit_group;\n" ::: "memory");
}
__device__ __forceinline__ void cpa_waitg0() {
    asm volatile("cp.async.wait_group 0;\n" ::: "memory");
}
__device__ __forceinline__ uint32_t cvt_f16x2(float hi, float lo) {
    uint32_t r;
    asm("cvt.rn.f16x2.f32 %0, %1, %2;" : "=r"(r) : "f"(hi), "f"(lo));
    return r;
}
__device__ __forceinline__ void sts64(uint32_t addr, uint32_t lo, uint32_t hi) {
    asm volatile("{\n\t.reg .b64 v;\n\tmov.b64 v, {%1, %2};\n\t"
                 "st.shared.b64 [%0], v;\n\t}" :: "r"(addr), "r"(lo), "r"(hi) : "memory");
}
__device__ __forceinline__ void stsv2(uint32_t addr, float x, float y) {
    asm volatile("st.shared.v2.f32 [%0], {%1, %2};" :: "r"(addr), "f"(x), "f"(y) : "memory");
}
__device__ __forceinline__ void stsz16(uint32_t addr) {
    asm volatile("st.shared.v4.b32 [%0], {%1, %1, %1, %1};" :: "r"(addr), "r"(0u) : "memory");
}
__device__ __forceinline__ uint32_t swz(uint32_t off) {
    return off ^ ((off >> 3) & 0x70);
}
__device__ __forceinline__ float sigmoidf_(float z) {
    return 1.0f / (1.0f + __expf(-z));
}
__device__ __forceinline__ void ldsm4(uint32_t* r, uint32_t addr) {
    asm volatile("ldmatrix.sync.aligned.m8n8.x4.shared.b16 {%0,%1,%2,%3}, [%4];"
                 : "=r"(r[0]), "=r"(r[1]), "=r"(r[2]), "=r"(r[3]) : "r"(addr));
}
__device__ __forceinline__ void hmma(float* c, const uint32_t* a, const uint32_t* b) {
    asm volatile(
        "mma.sync.aligned.m16n8k16.row.col.f32.f16.f16.f32 "
        "{%0,%1,%2,%3}, {%4,%5,%6,%7}, {%8,%9}, {%0,%1,%2,%3};"
        : "+f"(c[0]), "+f"(c[1]), "+f"(c[2]), "+f"(c[3])
        : "r"(a[0]), "r"(a[1]), "r"(a[2]), "r"(a[3]), "r"(b[0]), "r"(b[1]));
}
__device__ __forceinline__ void mbar_init(uint32_t a, uint32_t cnt) {
    asm volatile("mbarrier.init.shared.b64 [%0], %1;" :: "r"(a), "r"(cnt) : "memory");
}
__device__ __forceinline__ void mbar_arrive(uint32_t a) {
    asm volatile("mbarrier.arrive.release.cta.shared::cta.b64 _, [%0];" :: "r"(a) : "memory");
}
__device__ __forceinline__ void mbar_wait(uint32_t a, uint32_t parity) {
    asm volatile(
        "{\n\t.reg .pred P1;\n\t"
        "WL_%=:\n\t"
        "mbarrier.try_wait.parity.acquire.cta.shared::cta.b64 P1, [%0], %1, 0x989680;\n\t"
        "@P1 bra.uni WD_%=;\n\t"
        "bra.uni WL_%=;\n\t"
        "WD_%=:\n\t}"
        :: "r"(a), "r"(parity) : "memory");
}
__device__ __forceinline__ void barsync(int id, int cnt) {
    asm volatile("bar.sync %0, %1;" :: "r"(id), "r"(cnt) : "memory");
}

// -------- prep kernel: ctx mean (per batch) + x -> fp16 --------
__global__ void k_prep(const float* __restrict__ ctx, const float* __restrict__ x) {
    int b = blockIdx.x;                  // 64 blocks, 256 threads
    int t = threadIdx.x;
    #pragma unroll
    for (int i = 0; i < 4; i++) {
        int e = t + 256 * i;
        float2 v = reinterpret_cast<const float2*>(x + (size_t)b * Ii)[e];
        g_xh[b * (Ii / 2) + e] = cvt_f16x2(v.y, v.x);
    }
    __shared__ float sm[4];
    if (t < 128) {
        float4 v = reinterpret_cast<const float4*>(ctx + (size_t)b * Cc)[t];
        float s = v.x + v.y + v.z + v.w;
        #pragma unroll
        for (int off = 16; off; off >>= 1) s += __shfl_down_sync(0xffffffffu, s, off);
        if ((t & 31) == 0) sm[t >> 5] = s;
    }
    __syncthreads();
    if (t == 0)
        g_ctx_mean[b] = (sm[0] + sm[1] + sm[2] + sm[3]) * (1.0f / Cc);
}

// -------- main warp-specialized fp16 tensor kernel --------
// Grid 256 (No=8), 2 CTAs/SM. Warps 0-3: MMA consumers. Warps 4-7: producers,
// one (o, 4k) cell per thread per chunk. SINGLE change vs the 60.2us kernel:
// the 12 D/w/c LDG.128 are hoisted ABOVE the ring backpressure wait, so the
// chunk's DRAM burst is in flight during the wait (phase-lock fix).
__global__ void __launch_bounds__(NTHREADS, 2)
k_main(const float* __restrict__ dend,
       const float* __restrict__ weight,
       const float* __restrict__ cstr,
       const float* __restrict__ pthr,
       const float* __restrict__ gates,
       const float* __restrict__ bias,
       const float* __restrict__ aact,
       const float* __restrict__ athr,
       float* __restrict__ out) {
    extern __shared__ char smraw[];
    uint32_t sb0 = sa(smraw);
    uint32_t sb = (sb0 + 1023u) & ~1023u;
    char* smbase = smraw + (sb - sb0);
    float* epf = reinterpret_cast<float*>(smbase + SM_EP);
    float* maf = reinterpret_cast<float*>(smbase + SM_MA);

    const int t = threadIdx.x;
    const int lane = t & 31;
    const int o_base = blockIdx.x * No;

    const uint32_t FULLB = sb + SM_BAR;        // full[0..3] @ 0,8,16,24
    const uint32_t EMPTYB = sb + SM_BAR + 32;  // empty[0..3] @ 32,40,48,56
    const uint32_t aT0 = sb + SM_A;
    const uint32_t bT0 = sb + SM_B;

    if (t < 2 * STAGES) {
        // full: 4 producer-warp arrivals; empty: 4 consumer-warp arrivals
        mbar_init(sb + SM_BAR + t * 8, 4u);
    }
    // zero pad column rows (n % 12 == 11) of all 4 B buffers, once (256 = 4*8*8)
    {
        int st = t >> 6, rem = t & 63, ol = rem >> 3, seg = rem & 7;
        uint32_t n = (uint32_t)(ol * NCOL + 11);
        stsz16(bT0 + st * B_TILE + swz(n * 128 + seg * 16));
    }
    __syncthreads();

    if (t < 128) {
        // ================= CONSUMER (4 warps) =================
        const int w = t >> 5;
        const int wm = w & 1;
        const int wn = w >> 1;

        float acc[2][6][4];
        #pragma unroll
        for (int mt = 0; mt < 2; mt++)
            #pragma unroll
            for (int nt = 0; nt < 6; nt++)
                acc[mt][nt][0] = acc[mt][nt][1] = acc[mt][nt][2] = acc[mt][nt][3] = 0.0f;

        const int grp = lane >> 3;
        const uint32_t arow0 = (uint32_t)((wm * 32 + (lane & 15)) * 128 + (lane >> 4) * 16);
        const uint32_t arow1 = arow0 + 16 * 128;
        const uint32_t brow = (uint32_t)((wn * 48 + (grp >> 1) * 8 + (lane & 7)) * 128
                                         + (grp & 1) * 16);

        for (int c = 0; c < NCHUNKS; c++) {
            const int st = c & (STAGES - 1);
            mbar_wait(FULLB + st * 8, (c >> 2) & 1);

            const uint32_t ab = aT0 + st * A_TILE;
            const uint32_t bb = bT0 + st * B_TILE;
            #pragma unroll
            for (int ks = 0; ks < 4; ks++) {
                uint32_t a0[4], a1[4];
                ldsm4(a0, ab + swz(arow0 + ks * 32));
                ldsm4(a1, ab + swz(arow1 + ks * 32));
                #pragma unroll
                for (int pr = 0; pr < 3; pr++) {
                    uint32_t b4[4];
                    ldsm4(b4, bb + swz(brow + (uint32_t)pr * 2048 + ks * 32));
                    hmma(acc[0][2*pr],   a0, b4);
                    hmma(acc[0][2*pr+1], a0, b4 + 2);
                    hmma(acc[1][2*pr],   a1, b4);
                    hmma(acc[1][2*pr+1], a1, b4 + 2);
                }
            }
            __syncwarp();
            if (lane == 0) mbar_arrive(EMPTYB + st * 8);
        }

        // ---- epilogue: dump accumulators, compute mean-astro, combine ----
        barsync(5, 128);
        #pragma unroll
        for (int mt = 0; mt < 2; mt++) {
            int row = wm * 32 + mt * 16 + (lane >> 2);
            #pragma unroll
            for (int nt = 0; nt < 6; nt++) {
                int col = wn * 48 + nt * 8 + 2 * (lane & 3);
                stsv2(sb + SM_EP + (uint32_t)((row * EPW + col) * 4),
                      acc[mt][nt][0], acc[mt][nt][1]);
                stsv2(sb + SM_EP + (uint32_t)(((row + 8) * EPW + col) * 4),
                      acc[mt][nt][2], acc[mt][nt][3]);
            }
        }
        if (t < No) {
            float act = aact[o_base + t];
            float thv = athr[o_base + t];
            float s = 0.0f;
            #pragma unroll 8
            for (int b = 0; b < Bb; b++) {
                float a = 1.0f / (1.0f + expf(-g_ctx_mean[b] * act));
                s += (a > thv) ? a : 0.0f;
            }
            maf[t] = s * (1.0f / Bb);
        }
        barsync(5, 128);

        {
            const int ol = t & 7;
            const int bg = t >> 3;          // 0..15
            const int oo = o_base + ol;
            const float ma = maf[ol];
            const float bv = bias[oo];
            float sg[Ss];
            #pragma unroll
            for (int s = 0; s < Ss; s++) sg[s] = sigmoidf_(gates[oo * Ss + s]);
            #pragma unroll
            for (int j = 0; j < 4; j++) {
                int b = bg * 4 + j;
                const float* e = epf + b * EPW + ol * NCOL;
                float v = fmaf(e[10], ma, bv);
                #pragma unroll
                for (int s = 0; s < Ss; s++)
                    v = fmaf(sg[s], fmaxf(e[s], 0.0f), v);
                out[(size_t)b * Oo + oo] = fmaxf(v, 0.0f);
            }
        }
    } else {
        // ================= PRODUCER (4 warps) =================
        const int p = t - 128;           // 0..127
        const int o_loc = p >> 4;        // 0..7
        const int q = p & 15;            // k-quarter: k = 4q..4q+3
        const int o = o_base + o_loc;
        const int nrow = o_loc * NCOL;
        const float thr = pthr[0];
        const float* dsrc = dend + ((size_t)o * Ii + 4 * q) * Ss;
        const float* wsrc = weight + (size_t)o * Ii + 4 * q;
        const float* csrc = cstr + (size_t)o * Ii + 4 * q;

        for (int c = 0; c < NCHUNKS; c++) {
            const int st = c & (STAGES - 1);
            const int kb = c * KCH;

            // HOISTED: one (o, 4k) cell, 12 independent LDG.128 into registers —
            // these are in flight while we sit in the backpressure wait below.
            float4 d4[10];
            const float4* dp4 = reinterpret_cast<const float4*>(dsrc + (size_t)kb * Ss);
            #pragma unroll
            for (int j = 0; j < 10; j++) d4[j] = dp4[j];
            float4 w4 = *reinterpret_cast<const float4*>(wsrc + kb);
            float4 c4 = *reinterpret_cast<const float4*>(csrc + kb);

            if (c >= STAGES)
                mbar_wait(EMPTYB + st * 8, ((c - STAGES) >> 2) & 1);

            // A tile: x fp16 via cp.async, 512 x 16B over 128 threads
            #pragma unroll
            for (int r = 0; r < 4; r++) {
                int g = p + 128 * r;              // 0..511
                int b = g >> 3, sg_ = g & 7;
                const char* src = reinterpret_cast<const char*>(g_xh)
                                + ((size_t)b * Ii + kb + sg_ * 8) * 2;
                cpa16(aT0 + st * A_TILE + swz((uint32_t)b * 128 + sg_ * 16), src);
            }
            cpa_commit();

            // convert D cell + pruned weight column, STS into B tile
            float f[40];
            #pragma unroll
            for (int j = 0; j < 10; j++) {
                f[4*j] = d4[j].x; f[4*j+1] = d4[j].y;
                f[4*j+2] = d4[j].z; f[4*j+3] = d4[j].w;
            }
            float wv[4];
            wv[0] = (fabsf(w4.x) * c4.x > thr) ? w4.x : 0.0f;
            wv[1] = (fabsf(w4.y) * c4.y > thr) ? w4.y : 0.0f;
            wv[2] = (fabsf(w4.z) * c4.z > thr) ? w4.z : 0.0f;
            wv[3] = (fabsf(w4.w) * c4.w > thr) ? w4.w : 0.0f;

            const uint32_t bb = bT0 + st * B_TILE;
            #pragma unroll
            for (int s = 0; s < 11; s++) {
                float a0, a1, a2, a3;
                if (s < 10) { a0 = f[s]; a1 = f[10+s]; a2 = f[20+s]; a3 = f[30+s]; }
                else        { a0 = wv[0]; a1 = wv[1]; a2 = wv[2]; a3 = wv[3]; }
                uint32_t h0 = cvt_f16x2(a1, a0);
                uint32_t h1 = cvt_f16x2(a3, a2);
                sts64(bb + swz((uint32_t)(nrow + s) * 128 + q * 8), h0, h1);
            }

            cpa_waitg0();
            __syncwarp();
            if (lane == 0) mbar_arrive(FULLB + st * 8);
        }
    }
}

extern "C" void kernel_launch(void* const* d_in, const int* in_sizes, int n_in,
                              void* d_out, int out_size) {
    const float* x      = (const float*)d_in[0];
    const float* ctx    = (const float*)d_in[1];
    const float* weight = (const float*)d_in[3];
    const float* bias   = (const float*)d_in[4];
    const float* aact   = (const float*)d_in[5];
    const float* athr   = (const float*)d_in[6];
    const float* dend   = (const float*)d_in[7];
    const float* gates  = (const float*)d_in[8];
    const float* cstr   = (const float*)d_in[9];
    const float* pthr   = (const float*)d_in[10];
    float* out = (float*)d_out;

    cudaFuncSetAttribute(k_main, cudaFuncAttributeMaxDynamicSharedMemorySize, SMEM_REQ);

    k_prep<<<Bb, 256>>>(ctx, x);
    k_main<<<Oo / No, NTHREADS, SMEM_REQ>>>(dend, weight, cstr, pthr, gates, bias,
                                            aact, athr, out);
}